// round 12
// baseline (speedup 1.0000x reference)
#include <cuda_runtime.h>
#include <cuda_bf16.h>
#include <mma.h>
#include <math.h>

using namespace nvcuda;

#define NN 100000
#define DIM 128
#define HEADS 8
#define HD 16
#define EE 1600000
#define SLOPE 0.2f
#define LN_EPS 1e-5f
#define SCAN_B 98            // ceil(NN / 1024)

// ---------------- scratch (device globals; no allocation allowed) ----------------
__device__ float g_h[(size_t)NN * DIM];       // x @ W_gat
__device__ float g_asrc[NN * HEADS];
__device__ float g_adst[NN * HEADS];
__device__ float g_denom[NN * HEADS];         // sum of exp(e) per (node, head)
__device__ float g_agg[(size_t)NN * DIM];     // UNnormalized aggregated messages
__device__ int g_deg[NN];
__device__ int g_start[NN + 1];
__device__ int g_cursor[NN];
__device__ int g_csr[EE];                      // src ids grouped by dst
__device__ int g_btot[SCAN_B];
__device__ int g_boff[SCAN_B];
__device__ int g_is64;
// split-precision weights for tensor-core FFN
__device__ __nv_bfloat16 g_W1hi[DIM * 512];
__device__ __nv_bfloat16 g_W1lo[DIM * 512];
__device__ __nv_bfloat16 g_W2hi[512 * DIM];
__device__ __nv_bfloat16 g_W2lo[512 * DIM];

// ---------------- helpers ----------------
__device__ __forceinline__ float lrelu(float x) { return x > 0.f ? x : SLOPE * x; }

// packed f32x2 helpers (sm_103a)
__device__ __forceinline__ unsigned long long dup2(float x) {
    unsigned long long r; unsigned u = __float_as_uint(x);
    asm("mov.b64 %0, {%1, %2};" : "=l"(r) : "r"(u), "r"(u));
    return r;
}
__device__ __forceinline__ unsigned long long fma2(unsigned long long a, unsigned long long b, unsigned long long c) {
    unsigned long long d;
    asm("fma.rn.f32x2 %0, %1, %2, %3;" : "=l"(d) : "l"(a), "l"(b), "l"(c));
    return d;
}
__device__ __forceinline__ float2 unpk(unsigned long long v) {
    unsigned lo, hi;
    asm("mov.b64 {%0, %1}, %2;" : "=r"(lo), "=r"(hi) : "l"(v));
    return make_float2(__uint_as_float(lo), __uint_as_float(hi));
}

__device__ __forceinline__ int edge_val(const void* ei, int is64, size_t idx) {
    return is64 ? (int)((const long long*)ei)[idx] : ((const int*)ei)[idx];
}

// ============================================================================
// K0a: sniff edge_index dtype. int64 values < 2^31 -> every odd 32-bit word 0.
// ============================================================================
__global__ void k_detect(const unsigned* __restrict__ w) {
    unsigned nz = 0;
    for (int i = 1; i < 256; i += 2) nz |= w[i];
    g_is64 = (nz == 0) ? 1 : 0;
}

// K0b: zero degree histogram
__global__ void k_zero() {
    int i = blockIdx.x * blockDim.x + threadIdx.x;
    if (i < NN) g_deg[i] = 0;
}

// K0c: degree histogram over destinations (reads raw edge_index)
__global__ void k_hist(const void* __restrict__ ei) {
    int i = blockIdx.x * blockDim.x + threadIdx.x;
    if (i >= EE) return;
    int is64 = g_is64;
    int d = edge_val(ei, is64, (size_t)EE + i);
    atomicAdd(&g_deg[d], 1);
}

// K0d-1: per-block local exclusive scan + block totals
__global__ void __launch_bounds__(1024, 1) k_scan1() {
    __shared__ int warp_tot[32];
    int t = threadIdx.x, lane = t & 31, wid = t >> 5;
    int i = blockIdx.x * 1024 + t;
    int v = (i < NN) ? g_deg[i] : 0;
    int incl = v;
#pragma unroll
    for (int o = 1; o < 32; o <<= 1) {
        int n = __shfl_up_sync(0xffffffffu, incl, o);
        if (lane >= o) incl += n;
    }
    if (lane == 31) warp_tot[wid] = incl;
    __syncthreads();
    if (wid == 0) {
        int wv = warp_tot[lane];
        int wincl = wv;
#pragma unroll
        for (int o = 1; o < 32; o <<= 1) {
            int n = __shfl_up_sync(0xffffffffu, wincl, o);
            if (lane >= o) wincl += n;
        }
        warp_tot[lane] = wincl - wv;   // exclusive warp offsets
    }
    __syncthreads();
    int excl = warp_tot[wid] + (incl - v);
    if (i < NN) g_start[i] = excl;     // local (block-relative) for now
    if (t == 1023) g_btot[blockIdx.x] = excl + v;
}

// K0d-2: single block scans the 98 block totals -> exclusive offsets
__global__ void k_scan2() {
    int t = threadIdx.x;               // 128 threads
    __shared__ int wt[4];
    int lane = t & 31, wid = t >> 5;
    int v = (t < SCAN_B) ? g_btot[t] : 0;
    int incl = v;
#pragma unroll
    for (int o = 1; o < 32; o <<= 1) {
        int n = __shfl_up_sync(0xffffffffu, incl, o);
        if (lane >= o) incl += n;
    }
    if (lane == 31) wt[wid] = incl;
    __syncthreads();
    int off = 0;
    for (int ww = 0; ww < wid; ww++) off += wt[ww];
    if (t < SCAN_B) g_boff[t] = off + incl - v;
}

// K0d-3: add block offsets; init cursor
__global__ void __launch_bounds__(1024, 1) k_scan3() {
    int i = blockIdx.x * 1024 + threadIdx.x;
    if (i < NN) {
        int v = g_start[i] + g_boff[blockIdx.x];
        g_start[i] = v;
        g_cursor[i] = v;
    }
    if (i == 0) g_start[NN] = EE;
}

// K0e: scatter src ids into dst buckets (reads raw edge_index)
__global__ void k_scatter(const void* __restrict__ ei) {
    int i = blockIdx.x * blockDim.x + threadIdx.x;
    if (i >= EE) return;
    int is64 = g_is64;
    int s = edge_val(ei, is64, i);
    int d = edge_val(ei, is64, (size_t)EE + i);
    int pos = atomicAdd(&g_cursor[d], 1);
    g_csr[pos] = s;
}

// K0f: split W1/W2 into bf16 hi/lo pairs (one-time per launch; 65536 threads)
__global__ void k_cvtw(const float* __restrict__ W1, const float* __restrict__ W2) {
    int i = blockIdx.x * blockDim.x + threadIdx.x;
    if (i >= DIM * 512) return;
    float v1 = W1[i];
    __nv_bfloat16 h1b = __float2bfloat16(v1);
    g_W1hi[i] = h1b;
    g_W1lo[i] = __float2bfloat16(v1 - __bfloat162float(h1b));
    float v2 = W2[i];
    __nv_bfloat16 h2b = __float2bfloat16(v2);
    g_W2hi[i] = h2b;
    g_W2lo[i] = __float2bfloat16(v2 - __bfloat162float(h2b));
}

// ============================================================================
// K1: h = x @ W_gat (packed f32x2 FMA), attention dots, AND self-loop init of
//     g_agg / g_denom (acc values still in registers).
// ============================================================================
__global__ void __launch_bounds__(256, 1)
k_gat_gemm(const float* __restrict__ x,
           const float* __restrict__ Wg,
           const float* __restrict__ att_src,
           const float* __restrict__ att_dst) {
    extern __shared__ float sm[];
    float* Ws = sm;                 // 128*128
    float* xs = sm + DIM * DIM;     // 64*128
    __shared__ float as_s[DIM], ad_s[DIM];

    int t = threadIdx.x;            // 256 threads
    for (int i = t; i < DIM * DIM / 4; i += 256)
        ((float4*)Ws)[i] = ((const float4*)Wg)[i];
    if (t < DIM) { as_s[t] = att_src[t]; ad_s[t] = att_dst[t]; }

    int row0 = blockIdx.x * 64;
    int nrows = min(64, NN - row0);
    for (int i = t; i < nrows * 32; i += 256) {
        int r = i >> 5, c4 = i & 31;
        ((float4*)(xs + r * DIM))[c4] = ((const float4*)(x + (size_t)(row0 + r) * DIM))[c4];
    }
    __syncthreads();

    int lane = t & 31, w = t >> 5;
    int c0 = lane * 4;
    int rbase = w * 8;
    unsigned long long acc2[8][2];
#pragma unroll
    for (int r = 0; r < 8; r++) { acc2[r][0] = 0ull; acc2[r][1] = 0ull; }

    for (int k4 = 0; k4 < DIM; k4 += 4) {
        float4 xr[8];
#pragma unroll
        for (int r = 0; r < 8; r++)
            xr[r] = *(const float4*)(xs + (rbase + r) * DIM + k4);
#pragma unroll
        for (int kk = 0; kk < 4; kk++) {
            ulonglong2 wv = *(const ulonglong2*)(Ws + (k4 + kk) * DIM + c0);
#pragma unroll
            for (int r = 0; r < 8; r++) {
                float xv = (kk == 0) ? xr[r].x : (kk == 1) ? xr[r].y : (kk == 2) ? xr[r].z : xr[r].w;
                unsigned long long xd = dup2(xv);
                acc2[r][0] = fma2(xd, wv.x, acc2[r][0]);
                acc2[r][1] = fma2(xd, wv.y, acc2[r][1]);
            }
        }
    }

    int head = c0 >> 4;        // lane/4
    int cc = c0 & 15;
#pragma unroll
    for (int r = 0; r < 8; r++) {
        int row = rbase + r;
        bool live = row < nrows;
        float2 p0 = unpk(acc2[r][0]);
        float2 p1 = unpk(acc2[r][1]);
        float a0 = p0.x, a1 = p0.y, a2 = p1.x, a3 = p1.y;
        float ss = a0 * as_s[head * HD + cc] + a1 * as_s[head * HD + cc + 1]
                 + a2 * as_s[head * HD + cc + 2] + a3 * as_s[head * HD + cc + 3];
        float sd = a0 * ad_s[head * HD + cc] + a1 * ad_s[head * HD + cc + 1]
                 + a2 * ad_s[head * HD + cc + 2] + a3 * ad_s[head * HD + cc + 3];
        ss += __shfl_xor_sync(0xffffffffu, ss, 1);
        ss += __shfl_xor_sync(0xffffffffu, ss, 2);
        sd += __shfl_xor_sync(0xffffffffu, sd, 1);
        sd += __shfl_xor_sync(0xffffffffu, sd, 2);
        if (live) {
            size_t off = (size_t)(row0 + row) * DIM + c0;
            *(float4*)(g_h + off) = make_float4(a0, a1, a2, a3);
            // self-loop contribution (alpha numerator exp(lrelu(ss+sd)))
            float wgt = expf(lrelu(ss + sd));
            *(float4*)(g_agg + off) = make_float4(a0 * wgt, a1 * wgt, a2 * wgt, a3 * wgt);
            if ((lane & 3) == 0) {
                int nh = (row0 + row) * HEADS + head;
                g_asrc[nh] = ss;
                g_adst[nh] = sd;
                g_denom[nh] = wgt;
            }
        }
    }
}

// ============================================================================
// K2: CSR aggregation — one warp per destination node, 4 edges per iteration.
// ============================================================================
__global__ void __launch_bounds__(256, 8) k_agg() {
    int d = (blockIdx.x * blockDim.x + threadIdx.x) >> 5;
    if (d >= NN) return;
    int lane = threadIdx.x & 31;
    int head4 = lane >> 2;           // head owning this lane's 4 channels
    int h8 = lane & 7;               // head used in weight computation
    int egrp = lane >> 3;            // edge slot 0..3
    int c0 = lane * 4;

    int i0 = g_start[d], i1 = g_start[d + 1];
    if (i0 == i1) return;            // self-loop only; already initialized

    float adst_l = __ldg(&g_adst[d * HEADS + h8]);

    float accx = 0.f, accy = 0.f, accz = 0.f, accw = 0.f;
    float wsum = 0.f;

    for (int i = i0; i < i1; i += 4) {
        int idx = i + egrp;
        int sA = 0; float w = 0.f;
        if (idx < i1) {
            sA = __ldg(&g_csr[idx]);
            w = __expf(lrelu(__ldg(&g_asrc[sA * HEADS + h8]) + adst_l));
        }
        wsum += w;
        int rem = i1 - i;            // uniform across warp
#pragma unroll
        for (int e = 0; e < 4; e++) {
            if (e >= rem) break;
            int s = __shfl_sync(0xffffffffu, sA, e * 8);
            float wgt = __shfl_sync(0xffffffffu, w, e * 8 + head4);
            float4 hv = __ldg((const float4*)(g_h + (size_t)s * DIM + c0));
            accx = fmaf(wgt, hv.x, accx);
            accy = fmaf(wgt, hv.y, accy);
            accz = fmaf(wgt, hv.z, accz);
            accw = fmaf(wgt, hv.w, accw);
        }
    }

    wsum += __shfl_xor_sync(0xffffffffu, wsum, 8);
    wsum += __shfl_xor_sync(0xffffffffu, wsum, 16);

    float4* ap = (float4*)(g_agg + (size_t)d * DIM + c0);
    float4 cur = *ap;
    cur.x += accx; cur.y += accy; cur.z += accz; cur.w += accw;
    *ap = cur;
    if (lane < HEADS)
        g_denom[d * HEADS + lane] += wsum;
}

// ============================================================================
// K3: fused LN1 + tensor-core FFN (bf16x3, smem-staged weights) + residual + LN2
// smem layout (bytes):
//   [0,32768)        h1s   f32 [64][128]
//   [32768,65536)    Ahi/Alo bf16 [64][128] each; REUSED as outb f32 [64][128]
//   [65536,98304)    wshi bf16 [128][128]   (W1 or W2 slice, hi)
//   [98304,131072)   wslo bf16 [128][128]   (lo)
//   [131072,147456)  midhi bf16 [64][128]   (current kt tile)
//   [147456,163840)  midlo bf16 [64][128]
//   [163840,172032)  scratch f32: 8 warps x 256
//   [172032,174080)  b1s f32 [512]
//   [174080,174592)  b2s f32 [128]
// ============================================================================
#define SMEM_FFN_BYTES 174592

__global__ void __launch_bounds__(256, 1)
k_ffn(const float* __restrict__ x,
      const float* __restrict__ b_gat,
      const float* __restrict__ b1,
      const float* __restrict__ b2,
      const float* __restrict__ gamma,
      const float* __restrict__ beta,
      float* __restrict__ out) {
    extern __shared__ char smc[];
    float* h1s = (float*)smc;                                  // 64*128 f32
    __nv_bfloat16* Ahi = (__nv_bfloat16*)(smc + 32768);        // 64*128 bf16
    __nv_bfloat16* Alo = (__nv_bfloat16*)(smc + 49152);        // 64*128 bf16
    float* outb = (float*)(smc + 32768);                       // aliases Ahi/Alo
    __nv_bfloat16* wshi = (__nv_bfloat16*)(smc + 65536);       // 128*128 bf16
    __nv_bfloat16* wslo = (__nv_bfloat16*)(smc + 98304);       // 128*128 bf16
    __nv_bfloat16* midhi = (__nv_bfloat16*)(smc + 131072);     // 64*128 bf16
    __nv_bfloat16* midlo = (__nv_bfloat16*)(smc + 147456);     // 64*128 bf16
    float* scratch = (float*)(smc + 163840);                   // 8*256 f32
    float* b1s = (float*)(smc + 172032);                       // 512 f32
    float* b2s = (float*)(smc + 174080);                       // 128 f32

    int t = threadIdx.x;  // 256
    int lane = t & 31, w = t >> 5;
    int c0 = lane * 4;
    int rbase = w * 8;
    int head = c0 >> 4;
    int row0 = blockIdx.x * 64;
    int nrows = min(64, NN - row0);
    float* scr = scratch + w * 256;

    b1s[t] = b1[t];
    b1s[t + 256] = b1[t + 256];
    if (t < DIM) b2s[t] = b2[t];

    float4 gv = *(const float4*)(gamma + c0);
    float4 be = *(const float4*)(beta + c0);

    // ---- fused LN1 -> h1s (f32) + Ahi/Alo (bf16 split) ----
    {
        float4 bg = *(const float4*)(b_gat + c0);
#pragma unroll
        for (int r = 0; r < 8; r++) {
            int row = rbase + r;
            float o4x = 0.f, o4y = 0.f, o4z = 0.f, o4w = 0.f;
            if (row < nrows) {
                size_t off = (size_t)(row0 + row) * DIM + c0;
                float4 xv = *(const float4*)(x + off);
                float4 av = *(const float4*)(g_agg + off);
                float rd = 1.f / (g_denom[(row0 + row) * HEADS + head] + 1e-16f);
                float v[4] = {xv.x + av.x * rd + bg.x, xv.y + av.y * rd + bg.y,
                              xv.z + av.z * rd + bg.z, xv.w + av.w * rd + bg.w};
                float sum = v[0] + v[1] + v[2] + v[3];
#pragma unroll
                for (int o = 16; o > 0; o >>= 1) sum += __shfl_xor_sync(0xffffffffu, sum, o);
                float mu = sum * (1.f / DIM);
                float sq = 0.f;
#pragma unroll
                for (int j = 0; j < 4; j++) { float dd = v[j] - mu; sq += dd * dd; }
#pragma unroll
                for (int o = 16; o > 0; o >>= 1) sq += __shfl_xor_sync(0xffffffffu, sq, o);
                float rs = rsqrtf(sq * (1.f / DIM) + LN_EPS);
                o4x = gv.x * (v[0] - mu) * rs + be.x;
                o4y = gv.y * (v[1] - mu) * rs + be.y;
                o4z = gv.z * (v[2] - mu) * rs + be.z;
                o4w = gv.w * (v[3] - mu) * rs + be.w;
            }
            *(float4*)(h1s + row * DIM + c0) = make_float4(o4x, o4y, o4z, o4w);
            float vv[4] = {o4x, o4y, o4z, o4w};
#pragma unroll
            for (int j = 0; j < 4; j++) {
                __nv_bfloat16 hh = __float2bfloat16(vv[j]);
                Ahi[row * DIM + c0 + j] = hh;
                Alo[row * DIM + c0 + j] = __float2bfloat16(vv[j] - __bfloat162float(hh));
            }
        }
    }

    wmma::fragment<wmma::accumulator, 16, 16, 16, float> acc2[4];
#pragma unroll
    for (int m = 0; m < 4; m++) wmma::fill_fragment(acc2[m], 0.f);

    for (int kt = 0; kt < 4; kt++) {
        __syncthreads();   // ws free (and on kt=0: h1s/Ahi/Alo ready)
        // ---- stage W1 slice: rows k=0..127, cols kt*128..kt*128+127 ----
        for (int i = t; i < 2048; i += 256) {
            int k = i >> 4, j = i & 15;
            ((uint4*)wshi)[i] = ((const uint4*)(g_W1hi + (size_t)k * 512 + kt * 128))[j];
            ((uint4*)wslo)[i] = ((const uint4*)(g_W1lo + (size_t)k * 512 + kt * 128))[j];
        }
        __syncthreads();

        // ---- GEMM1 tile: mid(64x128) = A(64x128) @ W1slice(128x128) ----
        {
            wmma::fragment<wmma::accumulator, 16, 16, 16, float> a1[4];
#pragma unroll
            for (int m = 0; m < 4; m++) wmma::fill_fragment(a1[m], 0.f);
#pragma unroll
            for (int k = 0; k < 8; k++) {
                wmma::fragment<wmma::matrix_b, 16, 16, 16, __nv_bfloat16, wmma::row_major> bhi, blo;
                wmma::load_matrix_sync(bhi, wshi + (k * 16) * 128 + w * 16, 128);
                wmma::load_matrix_sync(blo, wslo + (k * 16) * 128 + w * 16, 128);
#pragma unroll
                for (int m = 0; m < 4; m++) {
                    wmma::fragment<wmma::matrix_a, 16, 16, 16, __nv_bfloat16, wmma::row_major> ahi, alo;
                    wmma::load_matrix_sync(ahi, Ahi + (m * 16) * DIM + k * 16, DIM);
                    wmma::load_matrix_sync(alo, Alo + (m * 16) * DIM + k * 16, DIM);
                    wmma::mma_sync(a1[m], ahi, bhi, a1[m]);
                    wmma::mma_sync(a1[m], ahi, blo, a1[m]);
                    wmma::mma_sync(a1[m], alo, bhi, a1[m]);
                }
            }
            // bias + exact GELU + bf16 split -> midhi/midlo (warp cols w*16..w*16+15)
#pragma unroll
            for (int m = 0; m < 4; m++) {
                wmma::store_matrix_sync(scr, a1[m], 16, wmma::mem_row_major);
                __syncwarp();
#pragma unroll
                for (int j = 0; j < 8; j++) {
                    int el = j * 32 + lane;
                    int r = el >> 4, c = el & 15;
                    float vv = scr[el] + b1s[kt * 128 + w * 16 + c];
                    vv = 0.5f * vv * (1.f + erff(vv * 0.70710678118654752f));
                    __nv_bfloat16 hh = __float2bfloat16(vv);
                    int mi = (m * 16 + r) * 128 + w * 16 + c;
                    midhi[mi] = hh;
                    midlo[mi] = __float2bfloat16(vv - __bfloat162float(hh));
                }
                __syncwarp();
            }
        }
        __syncthreads();   // mid ready; ws free

        // ---- stage W2 slice: rows kt*128..kt*128+127, all 128 cols (contiguous) ----
        for (int i = t; i < 2048; i += 256) {
            ((uint4*)wshi)[i] = ((const uint4*)(g_W2hi + (size_t)kt * 128 * DIM))[i];
            ((uint4*)wslo)[i] = ((const uint4*)(g_W2lo + (size_t)kt * 128 * DIM))[i];
        }
        __syncthreads();

        // ---- GEMM2 accumulate: acc2 += mid(64x128) @ W2slice(128x128) ----
#pragma unroll
        for (int k = 0; k < 8; k++) {
            wmma::fragment<wmma::matrix_b, 16, 16, 16, __nv_bfloat16, wmma::row_major> bhi, blo;
            wmma::load_matrix_sync(bhi, wshi + (k * 16) * 128 + w * 16, 128);
            wmma::load_matrix_sync(blo, wslo + (k * 16) * 128 + w * 16, 128);
#pragma unroll
            for (int m = 0; m < 4; m++) {
                wmma::fragment<wmma::matrix_a, 16, 16, 16, __nv_bfloat16, wmma::row_major> ahi, alo;
                wmma::load_matrix_sync(ahi, midhi + (m * 16) * 128 + k * 16, 128);
                wmma::load_matrix_sync(alo, midlo + (m * 16) * 128 + k * 16, 128);
                wmma::mma_sync(acc2[m], ahi, bhi, acc2[m]);
                wmma::mma_sync(acc2[m], ahi, blo, acc2[m]);
                wmma::mma_sync(acc2[m], alo, bhi, acc2[m]);
            }
        }
    }
    __syncthreads();       // all GEMM1 reads of Ahi/Alo done -> outb alias safe

    // ---- epilogue: outb = acc2 + b2 + h1 (residual); warp w owns cols w*16.. ----
#pragma unroll
    for (int m = 0; m < 4; m++) {
        wmma::store_matrix_sync(scr, acc2[m], 16, wmma::mem_row_major);
        __syncwarp();
#pragma unroll
        for (int j = 0; j < 8; j++) {
            int el = j * 32 + lane;
            int r = el >> 4, c = el & 15;
            int row = m * 16 + r;
            int col = w * 16 + c;
            outb[row * DIM + col] = scr[el] + b2s[col] + h1s[row * DIM + col];
        }
        __syncwarp();
    }
    __syncthreads();

    // ---- LN2 over outb rows ----
#pragma unroll
    for (int r = 0; r < 8; r++) {
        int row = rbase + r;
        if (row >= nrows) continue;
        float4 vv = *(const float4*)(outb + row * DIM + c0);
        float v[4] = {vv.x, vv.y, vv.z, vv.w};
        float sum = v[0] + v[1] + v[2] + v[3];
#pragma unroll
        for (int o = 16; o > 0; o >>= 1) sum += __shfl_xor_sync(0xffffffffu, sum, o);
        float mu = sum * (1.f / DIM);
        float sq = 0.f;
#pragma unroll
        for (int j = 0; j < 4; j++) { float dd = v[j] - mu; sq += dd * dd; }
#pragma unroll
        for (int o = 16; o > 0; o >>= 1) sq += __shfl_xor_sync(0xffffffffu, sq, o);
        float rs = rsqrtf(sq * (1.f / DIM) + LN_EPS);
        float4 o4;
        o4.x = gv.x * (v[0] - mu) * rs + be.x;
        o4.y = gv.y * (v[1] - mu) * rs + be.y;
        o4.z = gv.z * (v[2] - mu) * rs + be.z;
        o4.w = gv.w * (v[3] - mu) * rs + be.w;
        *(float4*)(out + (size_t)(row0 + row) * DIM + c0) = o4;
    }
}

// ============================================================================
extern "C" void kernel_launch(void* const* d_in, const int* in_sizes, int n_in,
                              void* d_out, int out_size) {
    const float* x        = (const float*)d_in[0];
    const void*  ei       = d_in[1];
    const float* W_gat    = (const float*)d_in[2];
    const float* att_src  = (const float*)d_in[3];
    const float* att_dst  = (const float*)d_in[4];
    const float* b_gat    = (const float*)d_in[5];
    const float* gamma    = (const float*)d_in[6];
    const float* beta     = (const float*)d_in[7];
    const float* W1       = (const float*)d_in[8];
    const float* b1       = (const float*)d_in[9];
    const float* W2       = (const float*)d_in[10];
    const float* b2       = (const float*)d_in[11];
    float* out = (float*)d_out;

    const int smem_gat = (DIM * DIM + 64 * DIM) * sizeof(float);   // 96 KB
    cudaFuncSetAttribute(k_gat_gemm, cudaFuncAttributeMaxDynamicSharedMemorySize, smem_gat);
    cudaFuncSetAttribute(k_ffn, cudaFuncAttributeMaxDynamicSharedMemorySize, SMEM_FFN_BYTES);

    const int rowBlocks = (NN + 63) / 64;   // 1563

    k_detect<<<1, 1>>>((const unsigned*)ei);
    k_zero<<<SCAN_B, 1024>>>();
    k_hist<<<(EE + 255) / 256, 256>>>(ei);
    k_cvtw<<<(DIM * 512 + 255) / 256, 256>>>(W1, W2);
    k_scan1<<<SCAN_B, 1024>>>();
    k_scan2<<<1, 128>>>();
    k_scan3<<<SCAN_B, 1024>>>();
    k_scatter<<<(EE + 255) / 256, 256>>>(ei);
    k_gat_gemm<<<rowBlocks, 256, smem_gat>>>(x, W_gat, att_src, att_dst);
    k_agg<<<(NN * 32 + 255) / 256, 256>>>();
    k_ffn<<<rowBlocks, 256, SMEM_FFN_BYTES>>>(x, b_gat, b1, b2, gamma, beta, out);
}

// round 13
// speedup vs baseline: 2.4577x; 2.4577x over previous
#include <cuda_runtime.h>
#include <cuda_bf16.h>
#include <math.h>

#define NN 100000
#define DIM 128
#define HEADS 8
#define HD 16
#define EE 1600000
#define SLOPE 0.2f
#define LN_EPS 1e-5f
#define SCAN_B 98            // ceil(NN / 1024)

// ---------------- scratch (device globals; no allocation allowed) ----------------
__device__ float g_h[(size_t)NN * DIM];       // x @ W_gat
__device__ float g_asrc[NN * HEADS];
__device__ float g_adst[NN * HEADS];
__device__ float g_denom[NN * HEADS];         // sum of exp(e) per (node, head)
__device__ float g_agg[(size_t)NN * DIM];     // UNnormalized aggregated messages
__device__ int g_deg[NN];
__device__ int g_start[NN + 1];
__device__ int g_cursor[NN];
__device__ int g_csr[EE];                      // src ids grouped by dst
__device__ int g_btot[SCAN_B];
__device__ int g_boff[SCAN_B];
__device__ int g_is64;

// ---------------- helpers ----------------
__device__ __forceinline__ float lrelu(float x) { return x > 0.f ? x : SLOPE * x; }

// packed f32x2 helpers (sm_103a)
__device__ __forceinline__ unsigned long long dup2(float x) {
    unsigned long long r; unsigned u = __float_as_uint(x);
    asm("mov.b64 %0, {%1, %2};" : "=l"(r) : "r"(u), "r"(u));
    return r;
}
__device__ __forceinline__ unsigned long long fma2(unsigned long long a, unsigned long long b, unsigned long long c) {
    unsigned long long d;
    asm("fma.rn.f32x2 %0, %1, %2, %3;" : "=l"(d) : "l"(a), "l"(b), "l"(c));
    return d;
}
__device__ __forceinline__ float2 unpk(unsigned long long v) {
    unsigned lo, hi;
    asm("mov.b64 {%0, %1}, %2;" : "=r"(lo), "=r"(hi) : "l"(v));
    return make_float2(__uint_as_float(lo), __uint_as_float(hi));
}

__device__ __forceinline__ int edge_val(const void* ei, int is64, size_t idx) {
    return is64 ? (int)((const long long*)ei)[idx] : ((const int*)ei)[idx];
}

// ============================================================================
// K0a: sniff edge_index dtype. int64 values < 2^31 -> every odd 32-bit word 0.
// ============================================================================
__global__ void k_detect(const unsigned* __restrict__ w) {
    unsigned nz = 0;
    for (int i = 1; i < 256; i += 2) nz |= w[i];
    g_is64 = (nz == 0) ? 1 : 0;
}

// K0b: zero degree histogram
__global__ void k_zero() {
    int i = blockIdx.x * blockDim.x + threadIdx.x;
    if (i < NN) g_deg[i] = 0;
}

// K0c: degree histogram over destinations (reads raw edge_index)
__global__ void k_hist(const void* __restrict__ ei) {
    int i = blockIdx.x * blockDim.x + threadIdx.x;
    if (i >= EE) return;
    int is64 = g_is64;
    int d = edge_val(ei, is64, (size_t)EE + i);
    atomicAdd(&g_deg[d], 1);
}

// K0d-1: per-block local exclusive scan + block totals
__global__ void __launch_bounds__(1024, 1) k_scan1() {
    __shared__ int warp_tot[32];
    int t = threadIdx.x, lane = t & 31, wid = t >> 5;
    int i = blockIdx.x * 1024 + t;
    int v = (i < NN) ? g_deg[i] : 0;
    int incl = v;
#pragma unroll
    for (int o = 1; o < 32; o <<= 1) {
        int n = __shfl_up_sync(0xffffffffu, incl, o);
        if (lane >= o) incl += n;
    }
    if (lane == 31) warp_tot[wid] = incl;
    __syncthreads();
    if (wid == 0) {
        int wv = warp_tot[lane];
        int wincl = wv;
#pragma unroll
        for (int o = 1; o < 32; o <<= 1) {
            int n = __shfl_up_sync(0xffffffffu, wincl, o);
            if (lane >= o) wincl += n;
        }
        warp_tot[lane] = wincl - wv;   // exclusive warp offsets
    }
    __syncthreads();
    int excl = warp_tot[wid] + (incl - v);
    if (i < NN) g_start[i] = excl;     // local (block-relative) for now
    if (t == 1023) g_btot[blockIdx.x] = excl + v;
}

// K0d-2: single block scans the 98 block totals -> exclusive offsets
__global__ void k_scan2() {
    int t = threadIdx.x;               // 128 threads
    __shared__ int wt[4];
    int lane = t & 31, wid = t >> 5;
    int v = (t < SCAN_B) ? g_btot[t] : 0;
    int incl = v;
#pragma unroll
    for (int o = 1; o < 32; o <<= 1) {
        int n = __shfl_up_sync(0xffffffffu, incl, o);
        if (lane >= o) incl += n;
    }
    if (lane == 31) wt[wid] = incl;
    __syncthreads();
    int off = 0;
    for (int ww = 0; ww < wid; ww++) off += wt[ww];
    if (t < SCAN_B) g_boff[t] = off + incl - v;
}

// K0d-3: add block offsets; init cursor
__global__ void __launch_bounds__(1024, 1) k_scan3() {
    int i = blockIdx.x * 1024 + threadIdx.x;
    if (i < NN) {
        int v = g_start[i] + g_boff[blockIdx.x];
        g_start[i] = v;
        g_cursor[i] = v;
    }
    if (i == 0) g_start[NN] = EE;
}

// K0e: scatter src ids into dst buckets (reads raw edge_index)
__global__ void k_scatter(const void* __restrict__ ei) {
    int i = blockIdx.x * blockDim.x + threadIdx.x;
    if (i >= EE) return;
    int is64 = g_is64;
    int s = edge_val(ei, is64, i);
    int d = edge_val(ei, is64, (size_t)EE + i);
    int pos = atomicAdd(&g_cursor[d], 1);
    g_csr[pos] = s;
}

// ============================================================================
// K1: h = x @ W_gat (packed f32x2 FMA), attention dots, AND self-loop init of
//     g_agg / g_denom (acc values still in registers).
// ============================================================================
__global__ void __launch_bounds__(256, 1)
k_gat_gemm(const float* __restrict__ x,
           const float* __restrict__ Wg,
           const float* __restrict__ att_src,
           const float* __restrict__ att_dst) {
    extern __shared__ float sm[];
    float* Ws = sm;                 // 128*128
    float* xs = sm + DIM * DIM;     // 64*128
    __shared__ float as_s[DIM], ad_s[DIM];

    int t = threadIdx.x;            // 256 threads
    for (int i = t; i < DIM * DIM / 4; i += 256)
        ((float4*)Ws)[i] = ((const float4*)Wg)[i];
    if (t < DIM) { as_s[t] = att_src[t]; ad_s[t] = att_dst[t]; }

    int row0 = blockIdx.x * 64;
    int nrows = min(64, NN - row0);
    for (int i = t; i < nrows * 32; i += 256) {
        int r = i >> 5, c4 = i & 31;
        ((float4*)(xs + r * DIM))[c4] = ((const float4*)(x + (size_t)(row0 + r) * DIM))[c4];
    }
    __syncthreads();

    int lane = t & 31, w = t >> 5;
    int c0 = lane * 4;
    int rbase = w * 8;
    unsigned long long acc2[8][2];
#pragma unroll
    for (int r = 0; r < 8; r++) { acc2[r][0] = 0ull; acc2[r][1] = 0ull; }

    for (int k4 = 0; k4 < DIM; k4 += 4) {
        float4 xr[8];
#pragma unroll
        for (int r = 0; r < 8; r++)
            xr[r] = *(const float4*)(xs + (rbase + r) * DIM + k4);
#pragma unroll
        for (int kk = 0; kk < 4; kk++) {
            ulonglong2 wv = *(const ulonglong2*)(Ws + (k4 + kk) * DIM + c0);
#pragma unroll
            for (int r = 0; r < 8; r++) {
                float xv = (kk == 0) ? xr[r].x : (kk == 1) ? xr[r].y : (kk == 2) ? xr[r].z : xr[r].w;
                unsigned long long xd = dup2(xv);
                acc2[r][0] = fma2(xd, wv.x, acc2[r][0]);
                acc2[r][1] = fma2(xd, wv.y, acc2[r][1]);
            }
        }
    }

    int head = c0 >> 4;        // lane/4
    int cc = c0 & 15;
#pragma unroll
    for (int r = 0; r < 8; r++) {
        int row = rbase + r;
        bool live = row < nrows;
        float2 p0 = unpk(acc2[r][0]);
        float2 p1 = unpk(acc2[r][1]);
        float a0 = p0.x, a1 = p0.y, a2 = p1.x, a3 = p1.y;
        float ss = a0 * as_s[head * HD + cc] + a1 * as_s[head * HD + cc + 1]
                 + a2 * as_s[head * HD + cc + 2] + a3 * as_s[head * HD + cc + 3];
        float sd = a0 * ad_s[head * HD + cc] + a1 * ad_s[head * HD + cc + 1]
                 + a2 * ad_s[head * HD + cc + 2] + a3 * ad_s[head * HD + cc + 3];
        ss += __shfl_xor_sync(0xffffffffu, ss, 1);
        ss += __shfl_xor_sync(0xffffffffu, ss, 2);
        sd += __shfl_xor_sync(0xffffffffu, sd, 1);
        sd += __shfl_xor_sync(0xffffffffu, sd, 2);
        if (live) {
            size_t off = (size_t)(row0 + row) * DIM + c0;
            *(float4*)(g_h + off) = make_float4(a0, a1, a2, a3);
            // self-loop contribution (alpha numerator exp(lrelu(ss+sd)))
            float wgt = expf(lrelu(ss + sd));
            *(float4*)(g_agg + off) = make_float4(a0 * wgt, a1 * wgt, a2 * wgt, a3 * wgt);
            if ((lane & 3) == 0) {
                int nh = (row0 + row) * HEADS + head;
                g_asrc[nh] = ss;
                g_adst[nh] = sd;
                g_denom[nh] = wgt;
            }
        }
    }
}

// ============================================================================
// K2: CSR aggregation — one warp per destination node, 4 edges per iteration.
// ============================================================================
__global__ void __launch_bounds__(256, 8) k_agg() {
    int d = (blockIdx.x * blockDim.x + threadIdx.x) >> 5;
    if (d >= NN) return;
    int lane = threadIdx.x & 31;
    int head4 = lane >> 2;           // head owning this lane's 4 channels
    int h8 = lane & 7;               // head used in weight computation
    int egrp = lane >> 3;            // edge slot 0..3
    int c0 = lane * 4;

    int i0 = g_start[d], i1 = g_start[d + 1];
    if (i0 == i1) return;            // self-loop only; already initialized

    float adst_l = __ldg(&g_adst[d * HEADS + h8]);

    float accx = 0.f, accy = 0.f, accz = 0.f, accw = 0.f;
    float wsum = 0.f;

    for (int i = i0; i < i1; i += 4) {
        int idx = i + egrp;
        int sA = 0; float w = 0.f;
        if (idx < i1) {
            sA = __ldg(&g_csr[idx]);
            w = __expf(lrelu(__ldg(&g_asrc[sA * HEADS + h8]) + adst_l));
        }
        wsum += w;
        int rem = i1 - i;            // uniform across warp
#pragma unroll
        for (int e = 0; e < 4; e++) {
            if (e >= rem) break;
            int s = __shfl_sync(0xffffffffu, sA, e * 8);
            float wgt = __shfl_sync(0xffffffffu, w, e * 8 + head4);
            float4 hv = __ldg((const float4*)(g_h + (size_t)s * DIM + c0));
            accx = fmaf(wgt, hv.x, accx);
            accy = fmaf(wgt, hv.y, accy);
            accz = fmaf(wgt, hv.z, accz);
            accw = fmaf(wgt, hv.w, accw);
        }
    }

    wsum += __shfl_xor_sync(0xffffffffu, wsum, 8);
    wsum += __shfl_xor_sync(0xffffffffu, wsum, 16);

    float4* ap = (float4*)(g_agg + (size_t)d * DIM + c0);
    float4 cur = *ap;
    cur.x += accx; cur.y += accy; cur.z += accz; cur.w += accw;
    *ap = cur;
    if (lane < HEADS)
        g_denom[d * HEADS + lane] += wsum;
}

// ============================================================================
// K3: fused LN1 + FFN + residual + LN2 — 128 rows/block, 512 threads.
// smem: h1s[128][128] f32 (64KB) | ws[128][128] f32 (64KB, W1-slice then
//       W2-slice per kt) | mids[128][128] f32 (64KB)  => 192KB.
// ============================================================================
__global__ void __launch_bounds__(512, 1)
k_ffn(const float* __restrict__ x,
      const float* __restrict__ b_gat,
      const float* __restrict__ W1,
      const float* __restrict__ b1,
      const float* __restrict__ W2,
      const float* __restrict__ b2,
      const float* __restrict__ gamma,
      const float* __restrict__ beta,
      float* __restrict__ out) {
    extern __shared__ float sm[];
    float* h1s  = sm;                        // 128*128
    float* ws   = sm + 128 * DIM;            // 128*128
    float* mids = ws + DIM * DIM;            // 128*128

    int t = threadIdx.x;  // 512
    int lane = t & 31, w = t >> 5;           // 16 warps
    int c0 = lane * 4;
    int rbase = w * 8;                       // rows 0..127
    int head = c0 >> 4;
    int row0 = blockIdx.x * 128;
    int nrows = min(128, NN - row0);

    float4 gv = *(const float4*)(gamma + c0);
    float4 be = *(const float4*)(beta + c0);

    // ---- fused LN1: each warp normalizes its own 8 rows into h1s ----
    {
        float4 bg = *(const float4*)(b_gat + c0);
#pragma unroll
        for (int r = 0; r < 8; r++) {
            int row = rbase + r;
            if (row < nrows) {
                size_t off = (size_t)(row0 + row) * DIM + c0;
                float4 xv = *(const float4*)(x + off);
                float4 av = *(const float4*)(g_agg + off);
                float rd = 1.f / (g_denom[(row0 + row) * HEADS + head] + 1e-16f);
                float v[4] = {xv.x + av.x * rd + bg.x, xv.y + av.y * rd + bg.y,
                              xv.z + av.z * rd + bg.z, xv.w + av.w * rd + bg.w};
                float sum = v[0] + v[1] + v[2] + v[3];
#pragma unroll
                for (int o = 16; o > 0; o >>= 1) sum += __shfl_xor_sync(0xffffffffu, sum, o);
                float mu = sum * (1.f / DIM);
                float sq = 0.f;
#pragma unroll
                for (int j = 0; j < 4; j++) { float dd = v[j] - mu; sq += dd * dd; }
#pragma unroll
                for (int o = 16; o > 0; o >>= 1) sq += __shfl_xor_sync(0xffffffffu, sq, o);
                float rs = rsqrtf(sq * (1.f / DIM) + LN_EPS);
                float4 o4;
                o4.x = gv.x * (v[0] - mu) * rs + be.x;
                o4.y = gv.y * (v[1] - mu) * rs + be.y;
                o4.z = gv.z * (v[2] - mu) * rs + be.z;
                o4.w = gv.w * (v[3] - mu) * rs + be.w;
                *(float4*)(h1s + row * DIM + c0) = o4;
            } else {
                *(float4*)(h1s + row * DIM + c0) = make_float4(0.f, 0.f, 0.f, 0.f);
            }
        }
    }

    unsigned long long acc2[8][2];
#pragma unroll
    for (int r = 0; r < 8; r++) { acc2[r][0] = 0ull; acc2[r][1] = 0ull; }

    for (int kt = 0; kt < 4; kt++) {
        __syncthreads();   // ws free from previous GEMM2 (kt=0: h1s ordering too)
        // ---- stage W1 slice: rows k=0..127, cols kt*128.. ----
        for (int i = t; i < DIM * 32; i += 512) {
            int k = i >> 5, c4 = i & 31;
            ((float4*)(ws + k * DIM))[c4] =
                ((const float4*)(W1 + (size_t)k * 512 + kt * DIM))[c4];
        }
        __syncthreads();

        // ---- GEMM1 tile: mid = h1 @ W1_tile + b1_tile ----
        unsigned long long m2[8][2];
        {
            float4 b1v = *(const float4*)(b1 + kt * DIM + c0);
            unsigned long long blo, bhi;
            asm("mov.b64 %0, {%1, %2};" : "=l"(blo) : "r"(__float_as_uint(b1v.x)), "r"(__float_as_uint(b1v.y)));
            asm("mov.b64 %0, {%1, %2};" : "=l"(bhi) : "r"(__float_as_uint(b1v.z)), "r"(__float_as_uint(b1v.w)));
#pragma unroll
            for (int r = 0; r < 8; r++) { m2[r][0] = blo; m2[r][1] = bhi; }
        }
        for (int k4 = 0; k4 < DIM; k4 += 4) {
            float4 xr[8];
#pragma unroll
            for (int r = 0; r < 8; r++)
                xr[r] = *(const float4*)(h1s + (rbase + r) * DIM + k4);
#pragma unroll
            for (int kk = 0; kk < 4; kk++) {
                ulonglong2 wv = *(const ulonglong2*)(ws + (k4 + kk) * DIM + c0);
#pragma unroll
                for (int r = 0; r < 8; r++) {
                    float xv = (kk == 0) ? xr[r].x : (kk == 1) ? xr[r].y : (kk == 2) ? xr[r].z : xr[r].w;
                    unsigned long long xd = dup2(xv);
                    m2[r][0] = fma2(xd, wv.x, m2[r][0]);
                    m2[r][1] = fma2(xd, wv.y, m2[r][1]);
                }
            }
        }
        // exact GELU -> mids (warp-private rows)
#pragma unroll
        for (int r = 0; r < 8; r++) {
            float2 p0 = unpk(m2[r][0]);
            float2 p1 = unpk(m2[r][1]);
            float mm[4] = {p0.x, p0.y, p1.x, p1.y};
#pragma unroll
            for (int j = 0; j < 4; j++)
                mm[j] = 0.5f * mm[j] * (1.f + erff(mm[j] * 0.70710678118654752f));
            *(float4*)(mids + (rbase + r) * DIM + c0) = make_float4(mm[0], mm[1], mm[2], mm[3]);
        }
        __syncthreads();   // all GEMM1 ws reads done; mids ready

        // ---- stage W2 slice: rows kt*128.., all 128 cols (contiguous) ----
        for (int i = t; i < DIM * 32; i += 512)
            ((float4*)ws)[i] = ((const float4*)(W2 + (size_t)kt * DIM * DIM))[i];
        __syncthreads();

        // ---- GEMM2 accumulate ----
        for (int k4 = 0; k4 < DIM; k4 += 4) {
            float4 xr[8];
#pragma unroll
            for (int r = 0; r < 8; r++)
                xr[r] = *(const float4*)(mids + (rbase + r) * DIM + k4);
#pragma unroll
            for (int kk = 0; kk < 4; kk++) {
                ulonglong2 wv = *(const ulonglong2*)(ws + (k4 + kk) * DIM + c0);
#pragma unroll
                for (int r = 0; r < 8; r++) {
                    float xv = (kk == 0) ? xr[r].x : (kk == 1) ? xr[r].y : (kk == 2) ? xr[r].z : xr[r].w;
                    unsigned long long xd = dup2(xv);
                    acc2[r][0] = fma2(xd, wv.x, acc2[r][0]);
                    acc2[r][1] = fma2(xd, wv.y, acc2[r][1]);
                }
            }
        }
    }

    // ---- residual + LN2 ----
    float4 b2v = *(const float4*)(b2 + c0);
#pragma unroll
    for (int r = 0; r < 8; r++) {
        int row = rbase + r;
        if (row >= nrows) continue;
        float2 p0 = unpk(acc2[r][0]);
        float2 p1 = unpk(acc2[r][1]);
        float v[4];
        v[0] = p0.x + b2v.x + h1s[row * DIM + c0 + 0];
        v[1] = p0.y + b2v.y + h1s[row * DIM + c0 + 1];
        v[2] = p1.x + b2v.z + h1s[row * DIM + c0 + 2];
        v[3] = p1.y + b2v.w + h1s[row * DIM + c0 + 3];
        float sum = v[0] + v[1] + v[2] + v[3];
#pragma unroll
        for (int o = 16; o > 0; o >>= 1) sum += __shfl_xor_sync(0xffffffffu, sum, o);
        float mu = sum * (1.f / DIM);
        float sq = 0.f;
#pragma unroll
        for (int j = 0; j < 4; j++) { float dd = v[j] - mu; sq += dd * dd; }
#pragma unroll
        for (int o = 16; o > 0; o >>= 1) sq += __shfl_xor_sync(0xffffffffu, sq, o);
        float rs = rsqrtf(sq * (1.f / DIM) + LN_EPS);
        float4 o4;
        o4.x = gv.x * (v[0] - mu) * rs + be.x;
        o4.y = gv.y * (v[1] - mu) * rs + be.y;
        o4.z = gv.z * (v[2] - mu) * rs + be.z;
        o4.w = gv.w * (v[3] - mu) * rs + be.w;
        *(float4*)(out + (size_t)(row0 + row) * DIM + c0) = o4;
    }
}

// ============================================================================
extern "C" void kernel_launch(void* const* d_in, const int* in_sizes, int n_in,
                              void* d_out, int out_size) {
    const float* x        = (const float*)d_in[0];
    const void*  ei       = d_in[1];
    const float* W_gat    = (const float*)d_in[2];
    const float* att_src  = (const float*)d_in[3];
    const float* att_dst  = (const float*)d_in[4];
    const float* b_gat    = (const float*)d_in[5];
    const float* gamma    = (const float*)d_in[6];
    const float* beta     = (const float*)d_in[7];
    const float* W1       = (const float*)d_in[8];
    const float* b1       = (const float*)d_in[9];
    const float* W2       = (const float*)d_in[10];
    const float* b2       = (const float*)d_in[11];
    float* out = (float*)d_out;

    const int smem_gat = (DIM * DIM + 64 * DIM) * sizeof(float);            // 96 KB
    const int smem_ffn = (128 * DIM + DIM * DIM + 128 * DIM) * sizeof(float); // 192 KB
    cudaFuncSetAttribute(k_gat_gemm, cudaFuncAttributeMaxDynamicSharedMemorySize, smem_gat);
    cudaFuncSetAttribute(k_ffn, cudaFuncAttributeMaxDynamicSharedMemorySize, smem_ffn);

    k_detect<<<1, 1>>>((const unsigned*)ei);
    k_zero<<<SCAN_B, 1024>>>();
    k_hist<<<(EE + 255) / 256, 256>>>(ei);
    k_scan1<<<SCAN_B, 1024>>>();
    k_scan2<<<1, 128>>>();
    k_scan3<<<SCAN_B, 1024>>>();
    k_scatter<<<(EE + 255) / 256, 256>>>(ei);
    k_gat_gemm<<<(NN + 63) / 64, 256, smem_gat>>>(x, W_gat, att_src, att_dst);
    k_agg<<<(NN * 32 + 255) / 256, 256>>>();
    k_ffn<<<(NN + 127) / 128, 512, smem_ffn>>>(x, b_gat, W1, b1, W2, b2, gamma, beta, out);
}

// round 16
// speedup vs baseline: 2.4777x; 1.0081x over previous
#include <cuda_runtime.h>
#include <cuda_bf16.h>
#include <math.h>

#define NN 100000
#define DIM 128
#define HEADS 8
#define HD 16
#define EE 1600000
#define SLOPE 0.2f
#define LN_EPS 1e-5f
#define SCAN_B 98            // ceil(NN / 1024)

// ---------------- scratch (device globals; no allocation allowed) ----------------
__device__ float g_h[(size_t)NN * DIM];       // x @ W_gat
__device__ float g_asrc[NN * HEADS];
__device__ float g_adst[NN * HEADS];
__device__ float g_denom[NN * HEADS];         // sum of exp(e) per (node, head)
__device__ float g_agg[(size_t)NN * DIM];     // UNnormalized aggregated messages
__device__ int g_deg[NN];
__device__ int g_start[NN + 1];
__device__ int g_cursor[NN];
__device__ int g_csr[EE];                      // src ids grouped by dst
__device__ int g_btot[SCAN_B];
__device__ int g_boff[SCAN_B];
__device__ int g_is64;

// ---------------- helpers ----------------
__device__ __forceinline__ float lrelu(float x) { return x > 0.f ? x : SLOPE * x; }

// packed f32x2 helpers (sm_103a)
__device__ __forceinline__ unsigned long long dup2(float x) {
    unsigned long long r; unsigned u = __float_as_uint(x);
    asm("mov.b64 %0, {%1, %2};" : "=l"(r) : "r"(u), "r"(u));
    return r;
}
__device__ __forceinline__ unsigned long long fma2(unsigned long long a, unsigned long long b, unsigned long long c) {
    unsigned long long d;
    asm("fma.rn.f32x2 %0, %1, %2, %3;" : "=l"(d) : "l"(a), "l"(b), "l"(c));
    return d;
}
__device__ __forceinline__ float2 unpk(unsigned long long v) {
    unsigned lo, hi;
    asm("mov.b64 {%0, %1}, %2;" : "=r"(lo), "=r"(hi) : "l"(v));
    return make_float2(__uint_as_float(lo), __uint_as_float(hi));
}

__device__ __forceinline__ int edge_val(const void* ei, int is64, size_t idx) {
    return is64 ? (int)((const long long*)ei)[idx] : ((const int*)ei)[idx];
}

// ============================================================================
// K0b: zero degree histogram; block 0 thread 0 also sniffs edge dtype
// (int64 values < 2^31 -> every odd 32-bit word is 0).
// ============================================================================
__global__ void k_zero(const unsigned* __restrict__ w) {
    int i = blockIdx.x * blockDim.x + threadIdx.x;
    if (i < NN) g_deg[i] = 0;
    if (i == 0) {
        unsigned nz = 0;
        for (int j = 1; j < 256; j += 2) nz |= w[j];
        g_is64 = (nz == 0) ? 1 : 0;
    }
}

// K0c: degree histogram over destinations (reads raw edge_index)
__global__ void k_hist(const void* __restrict__ ei) {
    int i = blockIdx.x * blockDim.x + threadIdx.x;
    if (i >= EE) return;
    int is64 = g_is64;
    int d = edge_val(ei, is64, (size_t)EE + i);
    atomicAdd(&g_deg[d], 1);
}

// K0d-1: per-block local exclusive scan + block totals
__global__ void __launch_bounds__(1024, 1) k_scan1() {
    __shared__ int warp_tot[32];
    int t = threadIdx.x, lane = t & 31, wid = t >> 5;
    int i = blockIdx.x * 1024 + t;
    int v = (i < NN) ? g_deg[i] : 0;
    int incl = v;
#pragma unroll
    for (int o = 1; o < 32; o <<= 1) {
        int n = __shfl_up_sync(0xffffffffu, incl, o);
        if (lane >= o) incl += n;
    }
    if (lane == 31) warp_tot[wid] = incl;
    __syncthreads();
    if (wid == 0) {
        int wv = warp_tot[lane];
        int wincl = wv;
#pragma unroll
        for (int o = 1; o < 32; o <<= 1) {
            int n = __shfl_up_sync(0xffffffffu, wincl, o);
            if (lane >= o) wincl += n;
        }
        warp_tot[lane] = wincl - wv;   // exclusive warp offsets
    }
    __syncthreads();
    int excl = warp_tot[wid] + (incl - v);
    if (i < NN) g_start[i] = excl;     // local (block-relative) for now
    if (t == 1023) g_btot[blockIdx.x] = excl + v;
}

// K0d-2: single block scans the 98 block totals -> exclusive offsets
__global__ void k_scan2() {
    int t = threadIdx.x;               // 128 threads
    __shared__ int wt[4];
    int lane = t & 31, wid = t >> 5;
    int v = (t < SCAN_B) ? g_btot[t] : 0;
    int incl = v;
#pragma unroll
    for (int o = 1; o < 32; o <<= 1) {
        int n = __shfl_up_sync(0xffffffffu, incl, o);
        if (lane >= o) incl += n;
    }
    if (lane == 31) wt[wid] = incl;
    __syncthreads();
    int off = 0;
    for (int ww = 0; ww < wid; ww++) off += wt[ww];
    if (t < SCAN_B) g_boff[t] = off + incl - v;
}

// K0d-3: add block offsets; init cursor
__global__ void __launch_bounds__(1024, 1) k_scan3() {
    int i = blockIdx.x * 1024 + threadIdx.x;
    if (i < NN) {
        int v = g_start[i] + g_boff[blockIdx.x];
        g_start[i] = v;
        g_cursor[i] = v;
    }
    if (i == 0) g_start[NN] = EE;
}

// K0e: scatter src ids into dst buckets (reads raw edge_index)
__global__ void k_scatter(const void* __restrict__ ei) {
    int i = blockIdx.x * blockDim.x + threadIdx.x;
    if (i >= EE) return;
    int is64 = g_is64;
    int s = edge_val(ei, is64, i);
    int d = edge_val(ei, is64, (size_t)EE + i);
    int pos = atomicAdd(&g_cursor[d], 1);
    g_csr[pos] = s;
}

// ============================================================================
// K1: h = x @ W_gat (packed f32x2 FMA), attention dots, AND self-loop init of
//     g_agg / g_denom (acc values still in registers).
// ============================================================================
__global__ void __launch_bounds__(256, 1)
k_gat_gemm(const float* __restrict__ x,
           const float* __restrict__ Wg,
           const float* __restrict__ att_src,
           const float* __restrict__ att_dst) {
    extern __shared__ float sm[];
    float* Ws = sm;                 // 128*128
    float* xs = sm + DIM * DIM;     // 64*128
    __shared__ float as_s[DIM], ad_s[DIM];

    int t = threadIdx.x;            // 256 threads
    for (int i = t; i < DIM * DIM / 4; i += 256)
        ((float4*)Ws)[i] = ((const float4*)Wg)[i];
    if (t < DIM) { as_s[t] = att_src[t]; ad_s[t] = att_dst[t]; }

    int row0 = blockIdx.x * 64;
    int nrows = min(64, NN - row0);
    for (int i = t; i < nrows * 32; i += 256) {
        int r = i >> 5, c4 = i & 31;
        ((float4*)(xs + r * DIM))[c4] = ((const float4*)(x + (size_t)(row0 + r) * DIM))[c4];
    }
    __syncthreads();

    int lane = t & 31, w = t >> 5;
    int c0 = lane * 4;
    int rbase = w * 8;
    unsigned long long acc2[8][2];
#pragma unroll
    for (int r = 0; r < 8; r++) { acc2[r][0] = 0ull; acc2[r][1] = 0ull; }

    for (int k4 = 0; k4 < DIM; k4 += 4) {
        float4 xr[8];
#pragma unroll
        for (int r = 0; r < 8; r++)
            xr[r] = *(const float4*)(xs + (rbase + r) * DIM + k4);
#pragma unroll
        for (int kk = 0; kk < 4; kk++) {
            ulonglong2 wv = *(const ulonglong2*)(Ws + (k4 + kk) * DIM + c0);
#pragma unroll
            for (int r = 0; r < 8; r++) {
                float xv = (kk == 0) ? xr[r].x : (kk == 1) ? xr[r].y : (kk == 2) ? xr[r].z : xr[r].w;
                unsigned long long xd = dup2(xv);
                acc2[r][0] = fma2(xd, wv.x, acc2[r][0]);
                acc2[r][1] = fma2(xd, wv.y, acc2[r][1]);
            }
        }
    }

    int head = c0 >> 4;        // lane/4
    int cc = c0 & 15;
#pragma unroll
    for (int r = 0; r < 8; r++) {
        int row = rbase + r;
        bool live = row < nrows;
        float2 p0 = unpk(acc2[r][0]);
        float2 p1 = unpk(acc2[r][1]);
        float a0 = p0.x, a1 = p0.y, a2 = p1.x, a3 = p1.y;
        float ss = a0 * as_s[head * HD + cc] + a1 * as_s[head * HD + cc + 1]
                 + a2 * as_s[head * HD + cc + 2] + a3 * as_s[head * HD + cc + 3];
        float sd = a0 * ad_s[head * HD + cc] + a1 * ad_s[head * HD + cc + 1]
                 + a2 * ad_s[head * HD + cc + 2] + a3 * ad_s[head * HD + cc + 3];
        ss += __shfl_xor_sync(0xffffffffu, ss, 1);
        ss += __shfl_xor_sync(0xffffffffu, ss, 2);
        sd += __shfl_xor_sync(0xffffffffu, sd, 1);
        sd += __shfl_xor_sync(0xffffffffu, sd, 2);
        if (live) {
            size_t off = (size_t)(row0 + row) * DIM + c0;
            *(float4*)(g_h + off) = make_float4(a0, a1, a2, a3);
            // self-loop contribution (alpha numerator exp(lrelu(ss+sd)))
            float wgt = expf(lrelu(ss + sd));
            *(float4*)(g_agg + off) = make_float4(a0 * wgt, a1 * wgt, a2 * wgt, a3 * wgt);
            if ((lane & 3) == 0) {
                int nh = (row0 + row) * HEADS + head;
                g_asrc[nh] = ss;
                g_adst[nh] = sd;
                g_denom[nh] = wgt;
            }
        }
    }
}

// ============================================================================
// K2: CSR aggregation — one warp per destination node, 8 edges per iteration
// (two 4-edge weight batches loaded up front -> 8 independent row gathers).
// ============================================================================
__global__ void __launch_bounds__(256, 8) k_agg() {
    int d = (blockIdx.x * blockDim.x + threadIdx.x) >> 5;
    if (d >= NN) return;
    int lane = threadIdx.x & 31;
    int head4 = lane >> 2;           // head owning this lane's 4 channels
    int h8 = lane & 7;               // head used in weight computation
    int egrp = lane >> 3;            // edge slot 0..3 within a 4-edge batch
    int c0 = lane * 4;

    int i0 = g_start[d], i1 = g_start[d + 1];
    if (i0 == i1) return;            // self-loop only; already initialized

    float adst_l = __ldg(&g_adst[d * HEADS + h8]);

    float accx = 0.f, accy = 0.f, accz = 0.f, accw = 0.f;
    float wsum = 0.f;

    for (int i = i0; i < i1; i += 8) {
        int idx0 = i + egrp;
        int idx1 = i + 4 + egrp;
        int sA0 = 0, sA1 = 0;
        float w0 = 0.f, w1 = 0.f;
        if (idx0 < i1) sA0 = __ldg(&g_csr[idx0]);
        if (idx1 < i1) sA1 = __ldg(&g_csr[idx1]);
        if (idx0 < i1) w0 = __expf(lrelu(__ldg(&g_asrc[sA0 * HEADS + h8]) + adst_l));
        if (idx1 < i1) w1 = __expf(lrelu(__ldg(&g_asrc[sA1 * HEADS + h8]) + adst_l));
        wsum += w0 + w1;
        int rem = i1 - i;            // uniform across warp
#pragma unroll
        for (int e = 0; e < 8; e++) {
            if (e >= rem) break;
            int s, src_lane = (e & 3) * 8;
            float wgt;
            if (e < 4) {
                s = __shfl_sync(0xffffffffu, sA0, src_lane);
                wgt = __shfl_sync(0xffffffffu, w0, src_lane + head4);
            } else {
                s = __shfl_sync(0xffffffffu, sA1, src_lane);
                wgt = __shfl_sync(0xffffffffu, w1, src_lane + head4);
            }
            float4 hv = __ldg((const float4*)(g_h + (size_t)s * DIM + c0));
            accx = fmaf(wgt, hv.x, accx);
            accy = fmaf(wgt, hv.y, accy);
            accz = fmaf(wgt, hv.z, accz);
            accw = fmaf(wgt, hv.w, accw);
        }
    }

    // per-head weight sums: combine the 4 edge groups (lanes h, h+8, h+16, h+24)
    wsum += __shfl_xor_sync(0xffffffffu, wsum, 8);
    wsum += __shfl_xor_sync(0xffffffffu, wsum, 16);

    // RMW (warp owns this node)
    float4* ap = (float4*)(g_agg + (size_t)d * DIM + c0);
    float4 cur = *ap;
    cur.x += accx; cur.y += accy; cur.z += accz; cur.w += accw;
    *ap = cur;
    if (lane < HEADS)
        g_denom[d * HEADS + lane] += wsum;
}

// ============================================================================
// K3: fused LN1 + FFN + residual + LN2 — 128 rows/block, 512 threads.
// smem: h1s[128][128] f32 (64KB) | ws[128][128] f32 (64KB, W1-slice then
//       W2-slice per kt) | mids[128][128] f32 (64KB)  => 192KB.
// ============================================================================
__global__ void __launch_bounds__(512, 1)
k_ffn(const float* __restrict__ x,
      const float* __restrict__ b_gat,
      const float* __restrict__ W1,
      const float* __restrict__ b1,
      const float* __restrict__ W2,
      const float* __restrict__ b2,
      const float* __restrict__ gamma,
      const float* __restrict__ beta,
      float* __restrict__ out) {
    extern __shared__ float sm[];
    float* h1s  = sm;                        // 128*128
    float* ws   = sm + 128 * DIM;            // 128*128
    float* mids = ws + DIM * DIM;            // 128*128

    int t = threadIdx.x;  // 512
    int lane = t & 31, w = t >> 5;           // 16 warps
    int c0 = lane * 4;
    int rbase = w * 8;                       // rows 0..127
    int head = c0 >> 4;
    int row0 = blockIdx.x * 128;
    int nrows = min(128, NN - row0);

    float4 gv = *(const float4*)(gamma + c0);
    float4 be = *(const float4*)(beta + c0);

    // ---- fused LN1: each warp normalizes its own 8 rows into h1s ----
    {
        float4 bg = *(const float4*)(b_gat + c0);
#pragma unroll
        for (int r = 0; r < 8; r++) {
            int row = rbase + r;
            if (row < nrows) {
                size_t off = (size_t)(row0 + row) * DIM + c0;
                float4 xv = *(const float4*)(x + off);
                float4 av = *(const float4*)(g_agg + off);
                float rd = 1.f / (g_denom[(row0 + row) * HEADS + head] + 1e-16f);
                float v[4] = {xv.x + av.x * rd + bg.x, xv.y + av.y * rd + bg.y,
                              xv.z + av.z * rd + bg.z, xv.w + av.w * rd + bg.w};
                float sum = v[0] + v[1] + v[2] + v[3];
#pragma unroll
                for (int o = 16; o > 0; o >>= 1) sum += __shfl_xor_sync(0xffffffffu, sum, o);
                float mu = sum * (1.f / DIM);
                float sq = 0.f;
#pragma unroll
                for (int j = 0; j < 4; j++) { float dd = v[j] - mu; sq += dd * dd; }
#pragma unroll
                for (int o = 16; o > 0; o >>= 1) sq += __shfl_xor_sync(0xffffffffu, sq, o);
                float rs = rsqrtf(sq * (1.f / DIM) + LN_EPS);
                float4 o4;
                o4.x = gv.x * (v[0] - mu) * rs + be.x;
                o4.y = gv.y * (v[1] - mu) * rs + be.y;
                o4.z = gv.z * (v[2] - mu) * rs + be.z;
                o4.w = gv.w * (v[3] - mu) * rs + be.w;
                *(float4*)(h1s + row * DIM + c0) = o4;
            } else {
                *(float4*)(h1s + row * DIM + c0) = make_float4(0.f, 0.f, 0.f, 0.f);
            }
        }
    }

    unsigned long long acc2[8][2];
#pragma unroll
    for (int r = 0; r < 8; r++) { acc2[r][0] = 0ull; acc2[r][1] = 0ull; }

    for (int kt = 0; kt < 4; kt++) {
        __syncthreads();   // ws free from previous GEMM2 (kt=0: h1s ordering too)
        // ---- stage W1 slice: rows k=0..127, cols kt*128.. ----
        for (int i = t; i < DIM * 32; i += 512) {
            int k = i >> 5, c4 = i & 31;
            ((float4*)(ws + k * DIM))[c4] =
                ((const float4*)(W1 + (size_t)k * 512 + kt * DIM))[c4];
        }
        __syncthreads();

        // ---- GEMM1 tile: mid = h1 @ W1_tile + b1_tile ----
        unsigned long long m2[8][2];
        {
            float4 b1v = *(const float4*)(b1 + kt * DIM + c0);
            unsigned long long blo, bhi;
            asm("mov.b64 %0, {%1, %2};" : "=l"(blo) : "r"(__float_as_uint(b1v.x)), "r"(__float_as_uint(b1v.y)));
            asm("mov.b64 %0, {%1, %2};" : "=l"(bhi) : "r"(__float_as_uint(b1v.z)), "r"(__float_as_uint(b1v.w)));
#pragma unroll
            for (int r = 0; r < 8; r++) { m2[r][0] = blo; m2[r][1] = bhi; }
        }
        for (int k4 = 0; k4 < DIM; k4 += 4) {
            float4 xr[8];
#pragma unroll
            for (int r = 0; r < 8; r++)
                xr[r] = *(const float4*)(h1s + (rbase + r) * DIM + k4);
#pragma unroll
            for (int kk = 0; kk < 4; kk++) {
                ulonglong2 wv = *(const ulonglong2*)(ws + (k4 + kk) * DIM + c0);
#pragma unroll
                for (int r = 0; r < 8; r++) {
                    float xv = (kk == 0) ? xr[r].x : (kk == 1) ? xr[r].y : (kk == 2) ? xr[r].z : xr[r].w;
                    unsigned long long xd = dup2(xv);
                    m2[r][0] = fma2(xd, wv.x, m2[r][0]);
                    m2[r][1] = fma2(xd, wv.y, m2[r][1]);
                }
            }
        }
        // exact GELU -> mids (warp-private rows)
#pragma unroll
        for (int r = 0; r < 8; r++) {
            float2 p0 = unpk(m2[r][0]);
            float2 p1 = unpk(m2[r][1]);
            float mm[4] = {p0.x, p0.y, p1.x, p1.y};
#pragma unroll
            for (int j = 0; j < 4; j++)
                mm[j] = 0.5f * mm[j] * (1.f + erff(mm[j] * 0.70710678118654752f));
            *(float4*)(mids + (rbase + r) * DIM + c0) = make_float4(mm[0], mm[1], mm[2], mm[3]);
        }
        __syncthreads();   // all GEMM1 ws reads done; mids ready

        // ---- stage W2 slice: rows kt*128.., all 128 cols (contiguous) ----
        for (int i = t; i < DIM * 32; i += 512)
            ((float4*)ws)[i] = ((const float4*)(W2 + (size_t)kt * DIM * DIM))[i];
        __syncthreads();

        // ---- GEMM2 accumulate ----
        for (int k4 = 0; k4 < DIM; k4 += 4) {
            float4 xr[8];
#pragma unroll
            for (int r = 0; r < 8; r++)
                xr[r] = *(const float4*)(mids + (rbase + r) * DIM + k4);
#pragma unroll
            for (int kk = 0; kk < 4; kk++) {
                ulonglong2 wv = *(const ulonglong2*)(ws + (k4 + kk) * DIM + c0);
#pragma unroll
                for (int r = 0; r < 8; r++) {
                    float xv = (kk == 0) ? xr[r].x : (kk == 1) ? xr[r].y : (kk == 2) ? xr[r].z : xr[r].w;
                    unsigned long long xd = dup2(xv);
                    acc2[r][0] = fma2(xd, wv.x, acc2[r][0]);
                    acc2[r][1] = fma2(xd, wv.y, acc2[r][1]);
                }
            }
        }
    }

    // ---- residual + LN2 ----
    float4 b2v = *(const float4*)(b2 + c0);
#pragma unroll
    for (int r = 0; r < 8; r++) {
        int row = rbase + r;
        if (row >= nrows) continue;
        float2 p0 = unpk(acc2[r][0]);
        float2 p1 = unpk(acc2[r][1]);
        float v[4];
        v[0] = p0.x + b2v.x + h1s[row * DIM + c0 + 0];
        v[1] = p0.y + b2v.y + h1s[row * DIM + c0 + 1];
        v[2] = p1.x + b2v.z + h1s[row * DIM + c0 + 2];
        v[3] = p1.y + b2v.w + h1s[row * DIM + c0 + 3];
        float sum = v[0] + v[1] + v[2] + v[3];
#pragma unroll
        for (int o = 16; o > 0; o >>= 1) sum += __shfl_xor_sync(0xffffffffu, sum, o);
        float mu = sum * (1.f / DIM);
        float sq = 0.f;
#pragma unroll
        for (int j = 0; j < 4; j++) { float dd = v[j] - mu; sq += dd * dd; }
#pragma unroll
        for (int o = 16; o > 0; o >>= 1) sq += __shfl_xor_sync(0xffffffffu, sq, o);
        float rs = rsqrtf(sq * (1.f / DIM) + LN_EPS);
        float4 o4;
        o4.x = gv.x * (v[0] - mu) * rs + be.x;
        o4.y = gv.y * (v[1] - mu) * rs + be.y;
        o4.z = gv.z * (v[2] - mu) * rs + be.z;
        o4.w = gv.w * (v[3] - mu) * rs + be.w;
        *(float4*)(out + (size_t)(row0 + row) * DIM + c0) = o4;
    }
}

// ============================================================================
extern "C" void kernel_launch(void* const* d_in, const int* in_sizes, int n_in,
                              void* d_out, int out_size) {
    const float* x        = (const float*)d_in[0];
    const void*  ei       = d_in[1];
    const float* W_gat    = (const float*)d_in[2];
    const float* att_src  = (const float*)d_in[3];
    const float* att_dst  = (const float*)d_in[4];
    const float* b_gat    = (const float*)d_in[5];
    const float* gamma    = (const float*)d_in[6];
    const float* beta     = (const float*)d_in[7];
    const float* W1       = (const float*)d_in[8];
    const float* b1       = (const float*)d_in[9];
    const float* W2       = (const float*)d_in[10];
    const float* b2       = (const float*)d_in[11];
    float* out = (float*)d_out;

    const int smem_gat = (DIM * DIM + 64 * DIM) * sizeof(float);            // 96 KB
    const int smem_ffn = (128 * DIM + DIM * DIM + 128 * DIM) * sizeof(float); // 192 KB
    cudaFuncSetAttribute(k_gat_gemm, cudaFuncAttributeMaxDynamicSharedMemorySize, smem_gat);
    cudaFuncSetAttribute(k_ffn, cudaFuncAttributeMaxDynamicSharedMemorySize, smem_ffn);

    k_zero<<<SCAN_B, 1024>>>((const unsigned*)ei);
    k_hist<<<(EE + 255) / 256, 256>>>(ei);
    k_scan1<<<SCAN_B, 1024>>>();
    k_scan2<<<1, 128>>>();
    k_scan3<<<SCAN_B, 1024>>>();
    k_scatter<<<(EE + 255) / 256, 256>>>(ei);
    k_gat_gemm<<<(NN + 63) / 64, 256, smem_gat>>>(x, W_gat, att_src, att_dst);
    k_agg<<<(NN * 32 + 255) / 256, 256>>>();
    k_ffn<<<(NN + 127) / 128, 512, smem_ffn>>>(x, b_gat, W1, b1, W2, b2, gamma, beta, out);
}